// round 2
// baseline (speedup 1.0000x reference)
#include <cuda_runtime.h>
#include <math.h>

#define B_TOT 65536
#define DH    256
#define BM    128     // batch rows per CTA
#define BN    32      // hidden cols (j) per CTA
#define KC    32      // K chunk
#define NGATE 6
#define STRIDE 36     // smem row stride in floats (pad: conflict-free frags)
#define THREADS 256

// ---- tf32 helpers -------------------------------------------------------
__device__ __forceinline__ unsigned f2tf32(float f) {
    unsigned u;
    asm("cvt.rna.tf32.f32 %0, %1;" : "=r"(u) : "f"(f));
    return u;
}

__device__ __forceinline__ void mma_tf32(float c[4], const unsigned a[4],
                                         unsigned b0, unsigned b1) {
    asm volatile(
        "mma.sync.aligned.m16n8k8.row.col.f32.tf32.tf32.f32 "
        "{%0,%1,%2,%3}, {%4,%5,%6,%7}, {%8,%9}, {%0,%1,%2,%3};"
        : "+f"(c[0]), "+f"(c[1]), "+f"(c[2]), "+f"(c[3])
        : "r"(a[0]), "r"(a[1]), "r"(a[2]), "r"(a[3]), "r"(b0), "r"(b1));
}

__device__ __forceinline__ float sigmoidf_(float x) {
    return 1.0f / (1.0f + expf(-x));
}

extern __shared__ unsigned smem_u[];

// smem carving (union of mainloop and epilogue):
//   mainloop: sA0 [128][36] u32, sA1 [128][36] u32, sW [192][36] u32  = 64512 B
//   epilogue: zs [128][193] f32                                       = 98816 B
#define SMEM_BYTES 98816

__global__ __launch_bounds__(THREADS, 1)
void share_lstm_kernel(const float* __restrict__ x,
                       const float* __restrict__ hm,
                       const float* __restrict__ cm,
                       const float* __restrict__ sm,
                       const float* __restrict__ mask,
                       const float* __restrict__ wih,
                       const float* __restrict__ whh,
                       const float* __restrict__ wsh,
                       const float* __restrict__ bih,
                       const float* __restrict__ bhh,
                       const float* __restrict__ bsh,
                       const int*   __restrict__ pidx,
                       float* __restrict__ out)
{
    const int m0   = blockIdx.x * BM;
    const int j0   = blockIdx.y * BN;
    const int tid  = threadIdx.x;
    const int lane = tid & 31;
    const int wid  = tid >> 5;
    const int warp_m = wid & 3;   // 0..3 -> 32 batch rows each
    const int warp_n = wid >> 2;  // 0..1 -> 3 gates each

    unsigned* sA0 = smem_u;                    // x (phase A) / h (phase B)
    unsigned* sA1 = smem_u + BM * STRIDE;      // s (phase B)
    unsigned* sW  = smem_u + 2 * BM * STRIDE;  // [gate*32+j][k]
    __shared__ float sBias[NGATE * BN];

    const int idx = *pidx;
    const float* sm0 = sm + (size_t)idx * (size_t)B_TOT * DH;

    // combined biases for this j tile
    if (tid < NGATE * BN) {
        const int g = tid >> 5, j = tid & 31;
        const int jj = j0 + j;
        float b = bih[g * DH + jj];
        b += (g < 4) ? bhh[g * DH + jj] : bsh[(g - 4) * DH + jj];
        sBias[tid] = b;
    }

    float acc[2][12][4];
    #pragma unroll
    for (int a = 0; a < 2; ++a)
        #pragma unroll
        for (int b = 0; b < 12; ++b)
            #pragma unroll
            for (int d = 0; d < 4; ++d) acc[a][b][d] = 0.0f;

    const int lr = tid >> 3;         // 0..31 : staging row
    const int lc = (tid & 7) << 2;   // 0..28 : staging col (float4)
    const int q  = lane >> 2;        // frag group
    const int cq = lane & 3;         // frag thread-in-group

    for (int ch = 0; ch < 16; ++ch) {
        const bool pA = (ch < 8);
        const int kg = ch * KC;              // global k in [0,512)
        const int kk = pA ? kg : kg - 256;   // k within second operand

        // ---- stage activations ----
        if (pA) {
            #pragma unroll
            for (int rr = lr; rr < BM; rr += 32) {
                const float4 v = *(const float4*)(x + (size_t)(m0 + rr) * DH + kg + lc);
                uint4 t = { f2tf32(v.x), f2tf32(v.y), f2tf32(v.z), f2tf32(v.w) };
                *(uint4*)(sA0 + rr * STRIDE + lc) = t;
            }
        } else {
            #pragma unroll
            for (int rr = lr; rr < BM; rr += 32) {
                const float4 vh = *(const float4*)(hm  + (size_t)(m0 + rr) * DH + kk + lc);
                const float4 vs = *(const float4*)(sm0 + (size_t)(m0 + rr) * DH + kk + lc);
                uint4 th = { f2tf32(vh.x), f2tf32(vh.y), f2tf32(vh.z), f2tf32(vh.w) };
                uint4 ts = { f2tf32(vs.x), f2tf32(vs.y), f2tf32(vs.z), f2tf32(vs.w) };
                *(uint4*)(sA0 + rr * STRIDE + lc) = th;
                *(uint4*)(sA1 + rr * STRIDE + lc) = ts;
            }
        }
        // ---- stage weights: 6 gates x 32 j x 32 k ----
        #pragma unroll
        for (int r = lr; r < NGATE * BN; r += 32) {
            const int g = r >> 5, j = r & 31;
            const float* wp;
            if (pA)           wp = wih + (size_t)(g * DH + j0 + j) * DH + kg;
            else if (g < 4)   wp = whh + (size_t)(g * DH + j0 + j) * DH + kk;
            else              wp = wsh + (size_t)((g - 4) * DH + j0 + j) * DH + kk;
            const float4 v = *(const float4*)(wp + lc);
            uint4 t = { f2tf32(v.x), f2tf32(v.y), f2tf32(v.z), f2tf32(v.w) };
            *(uint4*)(sW + r * STRIDE + lc) = t;
        }
        __syncthreads();

        // ---- mma over this K chunk ----
        #pragma unroll
        for (int ks = 0; ks < 4; ++ks) {
            const int kb = ks * 8 + cq;
            unsigned ah[2][4];
            unsigned as_[2][4];
            #pragma unroll
            for (int mf = 0; mf < 2; ++mf) {
                const int r = warp_m * 32 + mf * 16 + q;
                ah[mf][0] = sA0[(r    ) * STRIDE + kb];
                ah[mf][1] = sA0[(r + 8) * STRIDE + kb];
                ah[mf][2] = sA0[(r    ) * STRIDE + kb + 4];
                ah[mf][3] = sA0[(r + 8) * STRIDE + kb + 4];
            }
            if (!pA && warp_n == 1) {
                #pragma unroll
                for (int mf = 0; mf < 2; ++mf) {
                    const int r = warp_m * 32 + mf * 16 + q;
                    as_[mf][0] = sA1[(r    ) * STRIDE + kb];
                    as_[mf][1] = sA1[(r + 8) * STRIDE + kb];
                    as_[mf][2] = sA1[(r    ) * STRIDE + kb + 4];
                    as_[mf][3] = sA1[(r + 8) * STRIDE + kb + 4];
                }
            } else {
                #pragma unroll
                for (int mf = 0; mf < 2; ++mf)
                    #pragma unroll
                    for (int i = 0; i < 4; ++i) as_[mf][i] = ah[mf][i];
            }

            #pragma unroll
            for (int gl = 0; gl < 3; ++gl) {
                const int gate = warp_n * 3 + gl;
                // gates 4,5 (b-gates) take s in phase B; as_==ah otherwise
                const bool useS = (gate >= 4);
                unsigned au[2][4];
                #pragma unroll
                for (int mf = 0; mf < 2; ++mf)
                    #pragma unroll
                    for (int i = 0; i < 4; ++i)
                        au[mf][i] = useS ? as_[mf][i] : ah[mf][i];
                #pragma unroll
                for (int jf = 0; jf < 4; ++jf) {
                    const int nf = gl * 4 + jf;
                    const unsigned* wrow = sW + (gate * 32 + jf * 8 + q) * STRIDE + ks * 8 + cq;
                    const unsigned b0 = wrow[0];
                    const unsigned b1 = wrow[4];
                    mma_tf32(acc[0][nf], au[0], b0, b1);
                    mma_tf32(acc[1][nf], au[1], b0, b1);
                }
            }
        }
        __syncthreads();
    }

    // ---- epilogue: route accums through smem so each thread sees all 6 gates
    float* zs = (float*)smem_u;   // [128][193]
    #pragma unroll
    for (int mf = 0; mf < 2; ++mf) {
        #pragma unroll
        for (int nf = 0; nf < 12; ++nf) {
            const int gl = nf >> 2;
            const int gate = warp_n * 3 + gl;
            const int jb = (nf & 3) * 8;
            const int row = warp_m * 32 + mf * 16 + q;
            const int col = gate * 32 + jb + 2 * cq;
            zs[(row    ) * 193 + col    ] = acc[mf][nf][0];
            zs[(row    ) * 193 + col + 1] = acc[mf][nf][1];
            zs[(row + 8) * 193 + col    ] = acc[mf][nf][2];
            zs[(row + 8) * 193 + col + 1] = acc[mf][nf][3];
        }
    }
    __syncthreads();

    const size_t PLANE = (size_t)B_TOT * DH;
    for (int e = tid; e < BM * BN; e += THREADS) {
        const int m = e >> 5;
        const int j = e & 31;
        const int n = m0 + m;
        const int jj = j0 + j;
        const float* zrow = zs + (size_t)m * 193;
        const float zi  = zrow[      j] + sBias[      j];
        const float zf  = zrow[ 32 + j] + sBias[ 32 + j];
        const float zo  = zrow[ 64 + j] + sBias[ 64 + j];
        const float zc  = zrow[ 96 + j] + sBias[ 96 + j];
        const float zb0 = zrow[128 + j] + sBias[128 + j];
        const float zb1 = zrow[160 + j] + sBias[160 + j];

        const float ig  = sigmoidf_(zi);
        const float fg  = sigmoidf_(zf);
        const float og  = sigmoidf_(zo);
        const float bg0 = sigmoidf_(zb0);
        const float bg1 = sigmoidf_(zb1);

        const float mval = mask[n];
        const float cold = cm[(size_t)n * DH + jj];
        const float ct = (fg * cold + ig * tanhf(zc)) * mval;
        const float tc = tanhf(ct) * mval;

        const size_t base = (size_t)n * DH + jj;
        out[base            ] = og  * tc;  // h
        out[PLANE     + base] = ct;        // c_t
        out[2 * PLANE + base] = bg0 * tc;  // s0
        out[3 * PLANE + base] = bg1 * tc;  // s1
    }
}

extern "C" void kernel_launch(void* const* d_in, const int* in_sizes, int n_in,
                              void* d_out, int out_size) {
    (void)in_sizes; (void)n_in; (void)out_size;
    const float* x    = (const float*)d_in[0];
    const float* hm   = (const float*)d_in[1];
    const float* cm   = (const float*)d_in[2];
    const float* sm   = (const float*)d_in[3];
    const float* mask = (const float*)d_in[4];
    const float* wih  = (const float*)d_in[5];
    const float* whh  = (const float*)d_in[6];
    const float* wsh  = (const float*)d_in[7];
    const float* bih  = (const float*)d_in[8];
    const float* bhh  = (const float*)d_in[9];
    const float* bsh  = (const float*)d_in[10];
    const int*   idx  = (const int*)d_in[11];
    float* out = (float*)d_out;

    cudaFuncSetAttribute(share_lstm_kernel,
                         cudaFuncAttributeMaxDynamicSharedMemorySize, SMEM_BYTES);

    dim3 grid(B_TOT / BM, DH / BN);   // 512 x 8
    share_lstm_kernel<<<grid, THREADS, SMEM_BYTES>>>(
        x, hm, cm, sm, mask, wih, whh, wsh, bih, bhh, bsh, idx, out);
}

// round 3
// speedup vs baseline: 1.7865x; 1.7865x over previous
#include <cuda_runtime.h>
#include <cuda_fp16.h>
#include <math.h>

#define B_TOT 65536
#define DH    256
#define BM    128          // batch rows per CTA
#define BN    32           // hidden cols per CTA
#define KC    32           // K chunk
#define NGATE 6
#define SH    56           // smem row stride in halves (112B: conflict-free ldmatrix)
#define ROWS_TOT 448       // A0 128 + A1 128 + W 192
#define BUFH  (ROWS_TOT * SH)       // halves per buffer = 25088
#define THREADS 512
#define SMEM_BYTES (2 * BUFH * 2)   // 100352 B (epilogue zs 128x193 f32 = 98816 fits)

// ---- helpers ------------------------------------------------------------
__device__ __forceinline__ uint2 cvt2(float4 v) {
    __half2 h0 = __floats2half2_rn(v.x, v.y);
    __half2 h1 = __floats2half2_rn(v.z, v.w);
    uint2 r;
    r.x = *reinterpret_cast<unsigned*>(&h0);
    r.y = *reinterpret_cast<unsigned*>(&h1);
    return r;
}

__device__ __forceinline__ void ldsm4(unsigned r[4], const __half* p) {
    unsigned addr = (unsigned)__cvta_generic_to_shared(p);
    asm volatile("ldmatrix.sync.aligned.m8n8.x4.shared.b16 {%0,%1,%2,%3}, [%4];"
                 : "=r"(r[0]), "=r"(r[1]), "=r"(r[2]), "=r"(r[3]) : "r"(addr));
}

__device__ __forceinline__ void mma16816(float c[4], const unsigned a[4],
                                         unsigned b0, unsigned b1) {
    asm volatile(
        "mma.sync.aligned.m16n8k16.row.col.f32.f16.f16.f32 "
        "{%0,%1,%2,%3}, {%4,%5,%6,%7}, {%8,%9}, {%0,%1,%2,%3};"
        : "+f"(c[0]), "+f"(c[1]), "+f"(c[2]), "+f"(c[3])
        : "r"(a[0]), "r"(a[1]), "r"(a[2]), "r"(a[3]), "r"(b0), "r"(b1));
}

__device__ __forceinline__ float sigmoidf_(float x) {
    return 1.0f / (1.0f + expf(-x));
}

extern __shared__ __half smem_h[];

__global__ __launch_bounds__(THREADS, 1)
void share_lstm_kernel(const float* __restrict__ x,
                       const float* __restrict__ hm,
                       const float* __restrict__ cm,
                       const float* __restrict__ sm,
                       const float* __restrict__ mask,
                       const float* __restrict__ wih,
                       const float* __restrict__ whh,
                       const float* __restrict__ wsh,
                       const float* __restrict__ bih,
                       const float* __restrict__ bhh,
                       const float* __restrict__ bsh,
                       const int*   __restrict__ pidx,
                       float* __restrict__ out)
{
    const int j0   = blockIdx.x * BN;   // 8 j-tiles (fast dim -> L2 reuse of activations)
    const int m0   = blockIdx.y * BM;   // 512 batch tiles
    const int tid  = threadIdx.x;
    const int lane = tid & 31;
    const int wid  = tid >> 5;
    const int warp_m = wid & 7;         // 8 m-slices of 16 rows
    const int warp_n = wid >> 3;        // 2 gate-groups of 3 gates

    __shared__ float sBias[NGATE * BN];

    const int idx = *pidx;
    const float* sm0 = sm + (size_t)idx * (size_t)B_TOT * DH;

    if (tid < NGATE * BN) {
        const int g = tid >> 5, j = tid & 31;
        const int jj = j0 + j;
        float b = bih[g * DH + jj];
        b += (g < 4) ? bhh[g * DH + jj] : bsh[(g - 4) * DH + jj];
        sBias[tid] = b;
    }

    float acc[12][4];
    #pragma unroll
    for (int b = 0; b < 12; ++b)
        #pragma unroll
        for (int d = 0; d < 4; ++d) acc[b][d] = 0.0f;

    const int lr  = tid >> 3;           // 0..63 staging row
    const int lcf = (tid & 7) << 2;     // 0..28 staging col (floats)
    const int g4  = lane >> 3;          // ldmatrix quadrant
    const int l8  = lane & 7;

    float4 stA[2], stS[2], stW[3];

    // ---- producer: global -> regs (raw fp32) ----
    auto ldg_chunk = [&](int ch) {
        const bool pA = (ch < 8);
        const int kg = ch * KC;
        const int kk = pA ? kg : kg - 256;
        const float* aptr = pA ? x : hm;
        const int kc = pA ? kg : kk;
        #pragma unroll
        for (int i = 0; i < 2; ++i) {
            const int r = lr + 64 * i;
            stA[i] = *(const float4*)(aptr + (size_t)(m0 + r) * DH + kc + lcf);
            if (!pA)
                stS[i] = *(const float4*)(sm0 + (size_t)(m0 + r) * DH + kk + lcf);
        }
        #pragma unroll
        for (int i = 0; i < 3; ++i) {
            const int r = lr + 64 * i;        // 0..191
            const int g = r >> 5, j = r & 31;
            const float* wp;
            if (pA)         wp = wih + (size_t)(g * DH + j0 + j) * DH + kg;
            else if (g < 4) wp = whh + (size_t)(g * DH + j0 + j) * DH + kk;
            else            wp = wsh + (size_t)((g - 4) * DH + j0 + j) * DH + kk;
            stW[i] = *(const float4*)(wp + lcf);
        }
    };

    // ---- producer: regs -> smem (cvt to fp16) ----
    auto sts_chunk = [&](int ch, int b) {
        const bool pA = (ch < 8);
        __half* buf = smem_h + b * BUFH;
        const int lc2 = (tid & 7) << 2;   // half offset
        #pragma unroll
        for (int i = 0; i < 2; ++i) {
            const int r = lr + 64 * i;
            *(uint2*)(buf + r * SH + lc2) = cvt2(stA[i]);
            if (!pA)
                *(uint2*)(buf + (128 + r) * SH + lc2) = cvt2(stS[i]);
        }
        #pragma unroll
        for (int i = 0; i < 3; ++i) {
            const int r = lr + 64 * i;
            *(uint2*)(buf + (256 + r) * SH + lc2) = cvt2(stW[i]);
        }
    };

    // ---- consumer: mma over one K chunk ----
    auto mma_chunk = [&](int ch, int b) {
        const bool pA = (ch < 8);
        const __half* A0 = smem_h + b * BUFH;
        const __half* A1 = A0 + 128 * SH;
        const __half* W  = A0 + 256 * SH;
        #pragma unroll
        for (int kq = 0; kq < 2; ++kq) {
            const int k0 = kq * 16;
            unsigned a[4], as2[4];
            {
                const int row = warp_m * 16 + ((g4 & 1) << 3) + l8;
                const int kc  = k0 + ((g4 >> 1) << 3);
                ldsm4(a, A0 + row * SH + kc);
            }
            const bool needS = (!pA) && (warp_n == 1);
            if (needS) {
                const int row = warp_m * 16 + ((g4 & 1) << 3) + l8;
                const int kc  = k0 + ((g4 >> 1) << 3);
                ldsm4(as2, A1 + row * SH + kc);
            } else {
                #pragma unroll
                for (int i = 0; i < 4; ++i) as2[i] = a[i];
            }
            #pragma unroll
            for (int gl = 0; gl < 3; ++gl) {
                const int gate = warp_n * 3 + gl;
                const bool useS = (!pA) && (gate >= 4);
                unsigned au[4];
                #pragma unroll
                for (int i = 0; i < 4; ++i) au[i] = useS ? as2[i] : a[i];
                #pragma unroll
                for (int jh = 0; jh < 2; ++jh) {
                    unsigned bb[4];
                    const int row = gate * 32 + jh * 16 + ((g4 >> 1) << 3) + l8;
                    const int kc  = k0 + ((g4 & 1) << 3);
                    ldsm4(bb, W + row * SH + kc);
                    const int nf0 = gl * 4 + jh * 2;
                    mma16816(acc[nf0    ], au, bb[0], bb[1]);
                    mma16816(acc[nf0 + 1], au, bb[2], bb[3]);
                }
            }
        }
    };

    // ---- pipelined mainloop: 16 chunks, double-buffered ----
    ldg_chunk(0);
    sts_chunk(0, 0);
    for (int ch = 0; ch < 16; ++ch) {
        if (ch < 15) ldg_chunk(ch + 1);
        __syncthreads();
        mma_chunk(ch, ch & 1);
        if (ch < 15) sts_chunk(ch + 1, (ch + 1) & 1);
    }
    __syncthreads();

    // ---- epilogue: route accums through smem so each thread sees all 6 gates
    float* zs = (float*)smem_h;   // [128][193]
    const int q  = lane >> 2;
    const int cq = lane & 3;
    #pragma unroll
    for (int nf = 0; nf < 12; ++nf) {
        const int gl = nf >> 2;
        const int gate = warp_n * 3 + gl;
        const int jb = (nf & 3) * 8;
        const int row = warp_m * 16 + q;
        const int col = gate * 32 + jb + 2 * cq;
        zs[(row    ) * 193 + col    ] = acc[nf][0];
        zs[(row    ) * 193 + col + 1] = acc[nf][1];
        zs[(row + 8) * 193 + col    ] = acc[nf][2];
        zs[(row + 8) * 193 + col + 1] = acc[nf][3];
    }
    __syncthreads();

    const size_t PLANE = (size_t)B_TOT * DH;
    for (int e = tid; e < BM * BN; e += THREADS) {
        const int m = e >> 5;
        const int j = e & 31;
        const int n = m0 + m;
        const int jj = j0 + j;
        const float* zrow = zs + (size_t)m * 193;
        const float zi  = zrow[      j] + sBias[      j];
        const float zf  = zrow[ 32 + j] + sBias[ 32 + j];
        const float zo  = zrow[ 64 + j] + sBias[ 64 + j];
        const float zc  = zrow[ 96 + j] + sBias[ 96 + j];
        const float zb0 = zrow[128 + j] + sBias[128 + j];
        const float zb1 = zrow[160 + j] + sBias[160 + j];

        const float ig  = sigmoidf_(zi);
        const float fg  = sigmoidf_(zf);
        const float og  = sigmoidf_(zo);
        const float bg0 = sigmoidf_(zb0);
        const float bg1 = sigmoidf_(zb1);

        const float mval = mask[n];
        const float cold = cm[(size_t)n * DH + jj];
        const float ct = (fg * cold + ig * tanhf(zc)) * mval;
        const float tc = tanhf(ct) * mval;

        const size_t base = (size_t)n * DH + jj;
        out[base            ] = og  * tc;  // h
        out[PLANE     + base] = ct;        // c_t
        out[2 * PLANE + base] = bg0 * tc;  // s0
        out[3 * PLANE + base] = bg1 * tc;  // s1
    }
}

extern "C" void kernel_launch(void* const* d_in, const int* in_sizes, int n_in,
                              void* d_out, int out_size) {
    (void)in_sizes; (void)n_in; (void)out_size;
    const float* x    = (const float*)d_in[0];
    const float* hm   = (const float*)d_in[1];
    const float* cm   = (const float*)d_in[2];
    const float* sm   = (const float*)d_in[3];
    const float* mask = (const float*)d_in[4];
    const float* wih  = (const float*)d_in[5];
    const float* whh  = (const float*)d_in[6];
    const float* wsh  = (const float*)d_in[7];
    const float* bih  = (const float*)d_in[8];
    const float* bhh  = (const float*)d_in[9];
    const float* bsh  = (const float*)d_in[10];
    const int*   idx  = (const int*)d_in[11];
    float* out = (float*)d_out;

    cudaFuncSetAttribute(share_lstm_kernel,
                         cudaFuncAttributeMaxDynamicSharedMemorySize, SMEM_BYTES);

    dim3 grid(DH / BN, B_TOT / BM);   // (8, 512): j fast -> wave shares activations in L2
    share_lstm_kernel<<<grid, THREADS, SMEM_BYTES>>>(
        x, hm, cm, sm, mask, wih, whh, wsh, bih, bhh, bsh, idx, out);
}

// round 6
// speedup vs baseline: 2.0817x; 1.1653x over previous
#include <cuda_runtime.h>
#include <cuda_fp16.h>
#include <math.h>
#include <stdint.h>

#define B_TOT 65536
#define DH    256
#define BM    128
#define THREADS 384
#define NCH   8
#define KCH   64
#define SROW  144                 // smem row stride in bytes (72 halves)
#define OFF_S 18432               // 128*144
#define OFF_W 36864               // OFF_S + 128*144
#define BUFB  64512               // OFF_W + 192*144
#define SMEM_BYTES (3 * BUFB)     // 193536 (epilogue zs 128*193*4=98816 reuses)

// fp16 staging (device globals: allocation-free scratch)
__device__ __half g_xh[(size_t)B_TOT * 512];   // [m][0:256)=x, [256:512)=h
__device__ __half g_s [(size_t)B_TOT * 256];   // s[idx]
__device__ __half g_w [3072 * 256];            // [0,1536)=wih, [1536,2560)=whh, [2560,3072)=wsh

// ---------------- helpers ----------------
__device__ __forceinline__ unsigned sm_u32(const void* p) {
    return (unsigned)__cvta_generic_to_shared(const_cast<void*>(p));
}
__device__ __forceinline__ void cp16(void* dst, const void* src) {
    asm volatile("cp.async.cg.shared.global [%0], [%1], 16;"
                 :: "r"(sm_u32(dst)), "l"(src) : "memory");
}
__device__ __forceinline__ void ldsm4(unsigned r[4], const __half* p) {
    unsigned addr = sm_u32(p);
    asm volatile("ldmatrix.sync.aligned.m8n8.x4.shared.b16 {%0,%1,%2,%3}, [%4];"
                 : "=r"(r[0]), "=r"(r[1]), "=r"(r[2]), "=r"(r[3]) : "r"(addr));
}
__device__ __forceinline__ void mma16816(float c[4], const unsigned a[4],
                                         unsigned b0, unsigned b1) {
    asm volatile(
        "mma.sync.aligned.m16n8k16.row.col.f32.f16.f16.f32 "
        "{%0,%1,%2,%3}, {%4,%5,%6,%7}, {%8,%9}, {%0,%1,%2,%3};"
        : "+f"(c[0]), "+f"(c[1]), "+f"(c[2]), "+f"(c[3])
        : "r"(a[0]), "r"(a[1]), "r"(a[2]), "r"(a[3]), "r"(b0), "r"(b1));
}
__device__ __forceinline__ float sigmoidf_(float x) {
    return 1.0f / (1.0f + expf(-x));
}

// ---------------- conversion kernels ----------------
__global__ void cvt_xh_kernel(const float* __restrict__ x, const float* __restrict__ h) {
    const int N4 = B_TOT * (DH / 4);
    uint2* dst = (uint2*)g_xh;
    for (int t = blockIdx.x * blockDim.x + threadIdx.x; t < N4; t += gridDim.x * blockDim.x) {
        const int m = t >> 6, kq = t & 63;
        const float4 vx = ((const float4*)x)[t];
        const float4 vh = ((const float4*)h)[t];
        __half2 a0 = __floats2half2_rn(vx.x, vx.y), a1 = __floats2half2_rn(vx.z, vx.w);
        __half2 b0 = __floats2half2_rn(vh.x, vh.y), b1 = __floats2half2_rn(vh.z, vh.w);
        uint2 ua, ub;
        ua.x = *(unsigned*)&a0; ua.y = *(unsigned*)&a1;
        ub.x = *(unsigned*)&b0; ub.y = *(unsigned*)&b1;
        dst[m * 128 + kq]      = ua;
        dst[m * 128 + 64 + kq] = ub;
    }
}
__global__ void cvt_s_kernel(const float* __restrict__ s, const int* __restrict__ pidx) {
    const int N4 = B_TOT * (DH / 4);
    const float4* src = (const float4*)(s + (size_t)(*pidx) * B_TOT * DH);
    uint2* dst = (uint2*)g_s;
    for (int t = blockIdx.x * blockDim.x + threadIdx.x; t < N4; t += gridDim.x * blockDim.x) {
        const float4 v = src[t];
        __half2 a0 = __floats2half2_rn(v.x, v.y), a1 = __floats2half2_rn(v.z, v.w);
        uint2 u; u.x = *(unsigned*)&a0; u.y = *(unsigned*)&a1;
        dst[t] = u;
    }
}
__global__ void cvt_w_kernel(const float* __restrict__ wih, const float* __restrict__ whh,
                             const float* __restrict__ wsh) {
    const int N4 = 3072 * 64;
    uint2* dst = (uint2*)g_w;
    for (int t = blockIdx.x * blockDim.x + threadIdx.x; t < N4; t += gridDim.x * blockDim.x) {
        const int r = t >> 6, kq = t & 63;
        const float4* src;
        if (r < 1536)      src = (const float4*)wih + (size_t)r * 64 + kq;
        else if (r < 2560) src = (const float4*)whh + (size_t)(r - 1536) * 64 + kq;
        else               src = (const float4*)wsh + (size_t)(r - 2560) * 64 + kq;
        const float4 v = *src;
        __half2 a0 = __floats2half2_rn(v.x, v.y), a1 = __floats2half2_rn(v.z, v.w);
        uint2 u; u.x = *(unsigned*)&a0; u.y = *(unsigned*)&a1;
        dst[t] = u;
    }
}

// ---------------- GEMM + fused epilogue ----------------
__global__ __launch_bounds__(THREADS, 1)
void lstm_gemm_kernel(const float* __restrict__ cm,
                      const float* __restrict__ mask,
                      const float* __restrict__ bih,
                      const float* __restrict__ bhh,
                      const float* __restrict__ bsh,
                      float* __restrict__ out)
{
    extern __shared__ char smem[];
    __shared__ float sBias[192];

    const int tid  = threadIdx.x;
    const int lane = tid & 31;
    const int wid  = tid >> 5;
    const int warp_m = wid & 3;      // 4 m-warps * 32 rows
    const int warp_n = wid >> 2;     // 3 n-warps * 64 cols (gate pairs {0,1},{2,3},{4,5})
    const int j0 = blockIdx.x * 32;
    const int m0 = blockIdx.y * BM;

    if (tid < 192) {
        const int g = tid >> 5, j = tid & 31, jj = j0 + j;
        float b = bih[g * DH + jj];
        b += (g < 4) ? bhh[g * DH + jj] : bsh[(g - 4) * DH + jj];
        sBias[tid] = b;
    }

    float acc[2][8][4];
    #pragma unroll
    for (int a = 0; a < 2; ++a)
        #pragma unroll
        for (int b = 0; b < 8; ++b)
            #pragma unroll
            for (int d = 0; d < 4; ++d) acc[a][b][d] = 0.0f;

    // ---- stage one K-chunk into buffer ch%3 via cp.async ----
    auto stage = [&](int ch) {
        char* buf = smem + (ch % 3) * BUFB;
        // A = [x|h] rows, K contiguous 512
        #pragma unroll
        for (int idx = tid; idx < 1024; idx += THREADS) {
            const int r = idx >> 3, c = idx & 7;
            cp16(buf + r * SROW + c * 16,
                 g_xh + (size_t)(m0 + r) * 512 + ch * KCH + c * 8);
        }
        if (ch >= 4) {
            #pragma unroll
            for (int idx = tid; idx < 1024; idx += THREADS) {
                const int r = idx >> 3, c = idx & 7;
                cp16(buf + OFF_S + r * SROW + c * 16,
                     g_s + (size_t)(m0 + r) * 256 + (ch - 4) * KCH + c * 8);
            }
        }
        #pragma unroll
        for (int idx = tid; idx < 1536; idx += THREADS) {
            const int r = idx >> 3, c = idx & 7;   // r: gate*32 + j
            const int g = r >> 5, j = r & 31;
            int wr, kw;
            if (ch < 4)      { wr = g * 256 + j0 + j;                kw = ch * KCH; }
            else if (g < 4)  { wr = 1536 + g * 256 + j0 + j;         kw = (ch - 4) * KCH; }
            else             { wr = 2560 + (g - 4) * 256 + j0 + j;   kw = (ch - 4) * KCH; }
            cp16(buf + OFF_W + r * SROW + c * 16,
                 g_w + (size_t)wr * 256 + kw + c * 8);
        }
        asm volatile("cp.async.commit_group;" ::: "memory");
    };

    // ---- mma over one K chunk (4 x k16) ----
    const int arow = lane & 15;
    const int ak   = (lane & 16) >> 1;             // 0 / 8
    const int brow8 = ((lane >> 4) << 3) + (lane & 7);
    const int bk   = ((lane >> 3) & 1) << 3;       // 0 / 8

    auto mma_chunk = [&](int ch) {
        const char* buf = smem + (ch % 3) * BUFB;
        const __half* A = (const __half*)(buf + ((ch >= 4 && warp_n == 2) ? OFF_S : 0));
        const __half* W = (const __half*)(buf + OFF_W);
        #pragma unroll
        for (int kq = 0; kq < 4; ++kq) {
            unsigned a0[4], a1[4];
            ldsm4(a0, A + (warp_m * 32 +      arow) * 72 + kq * 16 + ak);
            ldsm4(a1, A + (warp_m * 32 + 16 + arow) * 72 + kq * 16 + ak);
            unsigned bb[4][4];
            #pragma unroll
            for (int nf2 = 0; nf2 < 4; ++nf2)
                ldsm4(bb[nf2], W + (warp_n * 64 + nf2 * 16 + brow8) * 72 + kq * 16 + bk);
            #pragma unroll
            for (int nf2 = 0; nf2 < 4; ++nf2) {
                mma16816(acc[0][nf2 * 2    ], a0, bb[nf2][0], bb[nf2][1]);
                mma16816(acc[0][nf2 * 2 + 1], a0, bb[nf2][2], bb[nf2][3]);
                mma16816(acc[1][nf2 * 2    ], a1, bb[nf2][0], bb[nf2][1]);
                mma16816(acc[1][nf2 * 2 + 1], a1, bb[nf2][2], bb[nf2][3]);
            }
        }
    };

    // ---- 3-stage pipelined mainloop, one sync per chunk ----
    stage(0);
    stage(1);
    for (int ch = 0; ch < NCH; ++ch) {
        if (ch < NCH - 1) asm volatile("cp.async.wait_group 1;" ::: "memory");
        else              asm volatile("cp.async.wait_group 0;" ::: "memory");
        __syncthreads();                       // buf ch ready; chunk ch-1 readers done
        if (ch + 2 < NCH) stage(ch + 2);       // overwrites buf read by chunk ch-1
        mma_chunk(ch);
    }
    __syncthreads();

    // ---- epilogue: accums -> smem so each thread sees all 6 gates ----
    float* zs = (float*)smem;   // [128][193]
    const int q  = lane >> 2;
    const int cq = lane & 3;
    #pragma unroll
    for (int mf = 0; mf < 2; ++mf)
        #pragma unroll
        for (int nf = 0; nf < 8; ++nf) {
            const int row = warp_m * 32 + mf * 16 + q;
            const int col = warp_n * 64 + nf * 8 + 2 * cq;
            zs[(row    ) * 193 + col    ] = acc[mf][nf][0];
            zs[(row    ) * 193 + col + 1] = acc[mf][nf][1];
            zs[(row + 8) * 193 + col    ] = acc[mf][nf][2];
            zs[(row + 8) * 193 + col + 1] = acc[mf][nf][3];
        }
    __syncthreads();

    const size_t PLANE = (size_t)B_TOT * DH;
    for (int e = tid; e < BM * 32; e += THREADS) {
        const int m = e >> 5;
        const int j = e & 31;
        const int n = m0 + m;
        const int jj = j0 + j;
        const float* zrow = zs + (size_t)m * 193;
        const float zi  = zrow[      j] + sBias[      j];
        const float zf  = zrow[ 32 + j] + sBias[ 32 + j];
        const float zo  = zrow[ 64 + j] + sBias[ 64 + j];
        const float zc  = zrow[ 96 + j] + sBias[ 96 + j];
        const float zb0 = zrow[128 + j] + sBias[128 + j];
        const float zb1 = zrow[160 + j] + sBias[160 + j];

        const float ig  = sigmoidf_(zi);
        const float fg  = sigmoidf_(zf);
        const float og  = sigmoidf_(zo);
        const float bg0 = sigmoidf_(zb0);
        const float bg1 = sigmoidf_(zb1);

        const float mval = mask[n];
        const float cold = cm[(size_t)n * DH + jj];
        const float ct = (fg * cold + ig * tanhf(zc)) * mval;
        const float tc = tanhf(ct) * mval;

        const size_t base = (size_t)n * DH + jj;
        out[base            ] = og  * tc;
        out[PLANE     + base] = ct;
        out[2 * PLANE + base] = bg0 * tc;
        out[3 * PLANE + base] = bg1 * tc;
    }
}

extern "C" void kernel_launch(void* const* d_in, const int* in_sizes, int n_in,
                              void* d_out, int out_size) {
    (void)in_sizes; (void)n_in; (void)out_size;
    const float* x    = (const float*)d_in[0];
    const float* hm   = (const float*)d_in[1];
    const float* cm   = (const float*)d_in[2];
    const float* sm   = (const float*)d_in[3];
    const float* mask = (const float*)d_in[4];
    const float* wih  = (const float*)d_in[5];
    const float* whh  = (const float*)d_in[6];
    const float* wsh  = (const float*)d_in[7];
    const float* bih  = (const float*)d_in[8];
    const float* bhh  = (const float*)d_in[9];
    const float* bsh  = (const float*)d_in[10];
    const int*   idx  = (const int*)d_in[11];
    float* out = (float*)d_out;

    cvt_xh_kernel<<<2048, 256>>>(x, hm);
    cvt_s_kernel<<<2048, 256>>>(sm, idx);
    cvt_w_kernel<<<768, 256>>>(wih, whh, wsh);

    cudaFuncSetAttribute(lstm_gemm_kernel,
                         cudaFuncAttributeMaxDynamicSharedMemorySize, SMEM_BYTES);
    dim3 grid(DH / 32, B_TOT / BM);   // (8, 512): j fast -> activation reuse in L2
    lstm_gemm_kernel<<<grid, THREADS, SMEM_BYTES>>>(cm, mask, bih, bhh, bsh, out);
}